// round 14
// baseline (speedup 1.0000x reference)
#include <cuda_runtime.h>
#include <cstdint>

// Problem constants (fixed by the dataset)
#define B_GRAPHS 256
#define NPG      128
#define N_TOT    (B_GRAPHS*NPG)   // 32768
#define FDIM     128
#define MLP_H    512
#define OUT_DIM  10
#define ROWCAP   64
#define CNT_OFF  2097152          // int offset of count region inside g_A

// ---------------- scratch: SAME symbol set / sizes as passing R1 -----------
__device__ float g_A[(size_t)B_GRAPHS*NPG*NPG];   // 16 MB: reused as csr+counts
__device__ float g_buf1[(size_t)N_TOT*FDIM];      // 16 MB  (X@W result)
__device__ float g_buf2[(size_t)N_TOT*FDIM];      // 16 MB  (aggregated H)
__device__ float g_dinv[N_TOT];                   // rsqrt(deg+1)
__device__ float g_mlp[B_GRAPHS*MLP_H];           // lin1 accumulator

// ---------------- zero scratch --------------------------------------------
__global__ void zero_scratch() {
    int i = blockIdx.x * 256 + threadIdx.x;       // grid 4096 -> i < 1,048,576
    float4 z = make_float4(0.f, 0.f, 0.f, 0.f);
    ((float4*)g_A)[i] = z;                        // zeroes csr + count regions
    if (i < N_TOT/4)            ((float4*)g_dinv)[i] = z;
    if (i < B_GRAPHS*MLP_H/4)   ((float4*)g_mlp)[i]  = z;
}

// ---------------- degree count + csr fill (one pass) -----------------------
__global__ void deg_kernel(const int* __restrict__ src,
                           const int* __restrict__ dst, int E) {
    int e = blockIdx.x * 256 + threadIdx.x;
    if (e < E) {
        int d = dst[e];
        int* base = (int*)g_A;
        int p = atomicAdd(base + CNT_OFF + d, 1);
        if (p < ROWCAP) base[(size_t)d * ROWCAP + p] = src[e] & 127;  // local id
    }
}
__global__ void dinv_kernel() {
    int i = blockIdx.x * 256 + threadIdx.x;
    if (i < N_TOT) {
        int c = ((const int*)g_A)[CNT_OFF + i];
        g_dinv[i] = rsqrtf((float)c + 1.0f);      // +1 = self loop
    }
}

// ============ 128x128-tile fp32 GEMM (256 thr, 8x8 micro) — proven R1 ======

// O[32768,128] = X[32768,128] @ W[128,128].  sel=0: X=Xext, sel=1: X=g_buf2.
__global__ void __launch_bounds__(256)
gemm_xw(const float* __restrict__ Xext, const float* __restrict__ W, int sel) {
    __shared__ __align__(16) float Ast[32][132];   // [k][row]
    __shared__ __align__(16) float Bs [32][132];   // [k][col]
    const float* __restrict__ X = sel ? g_buf2 : Xext;
    const int t = threadIdx.x;
    const int tx = t & 15, ty = t >> 4;
    const size_t row0 = (size_t)blockIdx.x * 128;

    float acc[8][8];
#pragma unroll
    for (int i = 0; i < 8; i++)
#pragma unroll
        for (int j = 0; j < 8; j++) acc[i][j] = 0.f;

    for (int kc = 0; kc < FDIM; kc += 32) {
#pragma unroll
        for (int q = 0; q < 4; q++) {             // X tile 128x32 (transposed)
            int idx = q * 256 + t;
            int r   = idx >> 3;
            int k4  = (idx & 7) << 2;
            float4 v = *(const float4*)(X + (row0 + r)*FDIM + kc + k4);
            Ast[k4+0][r] = v.x; Ast[k4+1][r] = v.y;
            Ast[k4+2][r] = v.z; Ast[k4+3][r] = v.w;
        }
#pragma unroll
        for (int q = 0; q < 4; q++) {             // W chunk 32x128
            int idx = q * 256 + t;
            int k   = idx >> 5;
            int c4  = (idx & 31) << 2;
            *(float4*)&Bs[k][c4] = *(const float4*)(W + (size_t)(kc+k)*FDIM + c4);
        }
        __syncthreads();
#pragma unroll
        for (int k = 0; k < 32; k++) {
            float a[8], b[8];
            *(float4*)&a[0] = *(const float4*)&Ast[k][ty*8];
            *(float4*)&a[4] = *(const float4*)&Ast[k][ty*8+4];
            *(float4*)&b[0] = *(const float4*)&Bs [k][tx*8];
            *(float4*)&b[4] = *(const float4*)&Bs [k][tx*8+4];
#pragma unroll
            for (int i = 0; i < 8; i++)
#pragma unroll
                for (int j = 0; j < 8; j++) acc[i][j] += a[i]*b[j];
        }
        __syncthreads();
    }
#pragma unroll
    for (int i = 0; i < 8; i++) {
        float4 v0 = make_float4(acc[i][0],acc[i][1],acc[i][2],acc[i][3]);
        float4 v1 = make_float4(acc[i][4],acc[i][5],acc[i][6],acc[i][7]);
        float* o = g_buf1 + (row0 + ty*8 + i)*FDIM + tx*8;
        *(float4*)o       = v0;
        *(float4*)(o + 4) = v1;
    }
}

// ---------------- aggregation (sparse gather body, same name/launch) -------
// g_buf2[d] = relu( dinv_d*( dinv_d*H[d] + sum_e dinv_s*H[s] ) + bias )
__global__ void __launch_bounds__(256)
agg_gemm(const float* __restrict__ bias) {
    __shared__ float Hs[128*68];
    __shared__ float sdinv[128];
    __shared__ int   scnt[128];
    const int g = blockIdx.x, t = threadIdx.x, w = t >> 5, l = t & 31;
    if (t < 128) {
        sdinv[t] = g_dinv[g*128 + t];
        int c = ((const int*)g_A)[CNT_OFF + g*128 + t];
        scnt[t] = c < ROWCAP ? c : ROWCAP;
    }
    const float* Hb  = g_buf1 + (size_t)g*NPG*FDIM;
    float*       Ob  = g_buf2 + (size_t)g*NPG*FDIM;
    const int*   csr = (const int*)g_A + (size_t)g*NPG*ROWCAP;

    for (int p = 0; p < 2; p++) {                  // two 64-feature passes
        if (p) __syncthreads();                    // drain previous pass readers
        for (int idx = t; idx < 2048; idx += 256) {
            int r = idx >> 4, c4 = (idx & 15) << 2;
            *(float4*)&Hs[r*68 + c4] = *(const float4*)(Hb + r*FDIM + p*64 + c4);
        }
        __syncthreads();
        const int f = p*64 + 2*l;
        const float b0 = bias[f], b1 = bias[f+1];
        for (int i = 0; i < 16; i++) {
            const int node = i*8 + w;
            const int cnt  = scnt[node];
            const int* cp  = csr + node*ROWCAP;
            const float dvd = sdinv[node];
            float2 hn = *(float2*)&Hs[node*68 + 2*l];
            float ax = dvd*hn.x, ay = dvd*hn.y;    // self-loop term
            for (int e = 0; e < cnt; e++) {
                int s = cp[e];
                float ds = sdinv[s];
                float2 h = *(float2*)&Hs[s*68 + 2*l];
                ax += ds*h.x; ay += ds*h.y;
            }
            float vx = ax*dvd + b0, vy = ay*dvd + b1;
            vx = vx > 0.f ? vx : 0.f;
            vy = vy > 0.f ? vy : 0.f;
            *(float2*)(Ob + node*FDIM + f) = make_float2(vx, vy);
        }
    }
}

// g_mlp[256,512] += H2[256,16384] @ lin1_w[16384,512]  (split-K=32, atomics)
__global__ void __launch_bounds__(256)
lin1_gemm(const float* __restrict__ W) {
    __shared__ __align__(16) float Ast[32][132];
    __shared__ __align__(16) float Bs [32][132];
    const int col0 = blockIdx.x * 128;   // 0..3
    const int row0 = blockIdx.y * 128;   // 0..1
    const int k0   = blockIdx.z * 512;   // 0..31
    const float* __restrict__ H2 = g_buf2;  // [256,16384] (node-major == reshape)
    const int t = threadIdx.x;
    const int tx = t & 15, ty = t >> 4;

    float acc[8][8];
#pragma unroll
    for (int i = 0; i < 8; i++)
#pragma unroll
        for (int j = 0; j < 8; j++) acc[i][j] = 0.f;

    for (int kc = 0; kc < 512; kc += 32) {
#pragma unroll
        for (int q = 0; q < 4; q++) {
            int idx = q * 256 + t;
            int r   = idx >> 3;
            int k4  = (idx & 7) << 2;
            float4 v = *(const float4*)(H2 + (size_t)(row0 + r)*16384 + k0 + kc + k4);
            Ast[k4+0][r] = v.x; Ast[k4+1][r] = v.y;
            Ast[k4+2][r] = v.z; Ast[k4+3][r] = v.w;
        }
#pragma unroll
        for (int q = 0; q < 4; q++) {
            int idx = q * 256 + t;
            int k   = idx >> 5;
            int c4  = (idx & 31) << 2;
            *(float4*)&Bs[k][c4] =
                *(const float4*)(W + (size_t)(k0 + kc + k)*MLP_H + col0 + c4);
        }
        __syncthreads();
#pragma unroll
        for (int k = 0; k < 32; k++) {
            float a[8], b[8];
            *(float4*)&a[0] = *(const float4*)&Ast[k][ty*8];
            *(float4*)&a[4] = *(const float4*)&Ast[k][ty*8+4];
            *(float4*)&b[0] = *(const float4*)&Bs [k][tx*8];
            *(float4*)&b[4] = *(const float4*)&Bs [k][tx*8+4];
#pragma unroll
            for (int i = 0; i < 8; i++)
#pragma unroll
                for (int j = 0; j < 8; j++) acc[i][j] += a[i]*b[j];
        }
        __syncthreads();
    }
#pragma unroll
    for (int i = 0; i < 8; i++)
#pragma unroll
        for (int j = 0; j < 8; j++)
            atomicAdd(&g_mlp[(size_t)(row0 + ty*8 + i)*MLP_H + col0 + tx*8 + j],
                      acc[i][j]);
}

__global__ void relu_bias_kernel(const float* __restrict__ b) {
    int i = blockIdx.x * 256 + threadIdx.x;
    if (i < B_GRAPHS*MLP_H) {
        float v = g_mlp[i] + b[i & (MLP_H-1)];
        g_mlp[i] = v > 0.f ? v : 0.f;
    }
}

// out[256,10] = g_mlp @ lin2_w + lin2_b.   One CTA per row, one warp per col.
__global__ void __launch_bounds__(320)
lin2_gemm(const float* __restrict__ W, const float* __restrict__ bias,
          float* __restrict__ out) {
    __shared__ float xr[MLP_H];
    const int m = blockIdx.x;
    const int w = threadIdx.x >> 5;      // 0..9
    const int lane = threadIdx.x & 31;
    for (int i = threadIdx.x; i < MLP_H; i += 320) xr[i] = g_mlp[(size_t)m*MLP_H + i];
    __syncthreads();
    float s = 0.f;
    for (int k = lane; k < MLP_H; k += 32) s += xr[k] * W[(size_t)k*OUT_DIM + w];
#pragma unroll
    for (int o = 16; o; o >>= 1) s += __shfl_xor_sync(0xffffffffu, s, o);
    if (lane == 0) out[(size_t)m*OUT_DIM + w] = s + bias[w];
}

// ---------------------------------------------------------------------------
extern "C" void kernel_launch(void* const* d_in, const int* in_sizes, int n_in,
                              void* d_out, int out_size) {
    const float* x   = (const float*)d_in[0];
    const int*   ei  = (const int*)  d_in[1];
    const float* W1  = (const float*)d_in[3];
    const float* b1  = (const float*)d_in[4];
    const float* W2  = (const float*)d_in[5];
    const float* b2  = (const float*)d_in[6];
    const float* l1w = (const float*)d_in[7];
    const float* l1b = (const float*)d_in[8];
    const float* l2w = (const float*)d_in[9];
    const float* l2b = (const float*)d_in[10];
    float* out = (float*)d_out;

    const int E = in_sizes[1] / 2;
    const int* src = ei;
    const int* dst = ei + E;
    const int eg = (E + 255) / 256;

    zero_scratch <<<4096, 256>>>();
    deg_kernel   <<<eg, 256>>>(src, dst, E);    // count + csr fill
    dinv_kernel  <<<N_TOT/256, 256>>>();

    // layer 1
    gemm_xw  <<<256, 256>>>(x, W1, 0);      // g_buf1 = x @ W1
    agg_gemm <<<256, 256>>>(b1);            // g_buf2 = relu(A@g_buf1 + b1)
    // layer 2
    gemm_xw  <<<256, 256>>>(x, W2, 1);      // g_buf1 = g_buf2 @ W2
    agg_gemm <<<256, 256>>>(b2);            // g_buf2 = relu(A@g_buf1 + b2)

    // MLP
    lin1_gemm <<<dim3(4, 2, 32), 256>>>(l1w);
    relu_bias_kernel <<<(B_GRAPHS*MLP_H + 255)/256, 256>>>(l1b);
    lin2_gemm <<<B_GRAPHS, 320>>>(l2w, l2b, out);
}

// round 16
// speedup vs baseline: 1.1826x; 1.1826x over previous
#include <cuda_runtime.h>
#include <cstdint>

// Problem constants (fixed by the dataset)
#define B_GRAPHS 256
#define NPG      128
#define N_TOT    (B_GRAPHS*NPG)   // 32768
#define FDIM     128
#define MLP_H    512
#define OUT_DIM  10
#define ROWCAP   64
#define CNT_OFF  2097152          // int offset of count region inside g_A
#define CH       2112             // 16*132 floats per staged tile

// ---------------- scratch: SAME symbol set / sizes as passing R14 ----------
__device__ float g_A[(size_t)B_GRAPHS*NPG*NPG];   // 16 MB: csr rows + counts
__device__ float g_buf1[(size_t)N_TOT*FDIM];      // kept for symbol stability
__device__ float g_buf2[(size_t)N_TOT*FDIM];      // layer output H
__device__ float g_dinv[N_TOT];                   // rsqrt(deg+1)
__device__ float g_mlp[B_GRAPHS*MLP_H];           // lin1 accumulator

// ---------------- prep ------------------------------------------------------
__global__ void zero_scratch() {
    int i = blockIdx.x * 256 + threadIdx.x;       // grid 512
    if (i < N_TOT)          ((int*)g_A)[CNT_OFF + i] = 0;
    if (i < B_GRAPHS*MLP_H) g_mlp[i] = 0.f;
}
__global__ void deg_kernel(const int* __restrict__ src,
                           const int* __restrict__ dst, int E) {
    int e = blockIdx.x * 256 + threadIdx.x;
    if (e < E) {
        int d = dst[e];
        int* base = (int*)g_A;
        int p = atomicAdd(base + CNT_OFF + d, 1);
        if (p < ROWCAP) base[(size_t)d * ROWCAP + p] = src[e] & 127;  // local id
    }
}
__global__ void dinv_kernel() {
    int i = blockIdx.x * 256 + threadIdx.x;
    if (i < N_TOT) {
        int c = ((const int*)g_A)[CNT_OFF + i];
        g_dinv[i] = rsqrtf((float)c + 1.0f);      // +1 = self loop
    }
}

// ---------------- staging macros (16-k chunk, 2 float4 per thread each) ----
#define LOAD_AB(Aptr, ldA, Bptr, ldB, kc)                                   \
    _Pragma("unroll")                                                       \
    for (int q = 0; q < 2; q++) {                                           \
        int idx = q * 256 + t;                                              \
        int r = idx >> 2, k4 = (idx & 3) << 2;                              \
        pA[q] = *(const float4*)((Aptr) + (size_t)r * (ldA) + (kc) + k4);   \
        int kk = idx >> 5, c4 = (idx & 31) << 2;                            \
        pB[q] = *(const float4*)((Bptr) + (size_t)((kc) + kk) * (ldB) + c4);\
    }
#define STORE_AB(buf)                                                       \
    _Pragma("unroll")                                                       \
    for (int q = 0; q < 2; q++) {                                           \
        int idx = q * 256 + t;                                              \
        int r = idx >> 2, k4 = (idx & 3) << 2;                              \
        (buf)[(k4+0)*132 + r] = pA[q].x;                                    \
        (buf)[(k4+1)*132 + r] = pA[q].y;                                    \
        (buf)[(k4+2)*132 + r] = pA[q].z;                                    \
        (buf)[(k4+3)*132 + r] = pA[q].w;                                    \
        int kk = idx >> 5, c4 = (idx & 31) << 2;                            \
        *(float4*)&(buf)[CH + kk*132 + c4] = pB[q];                         \
    }
#define FRAG_FMA(Xs, Ws)                                                    \
    _Pragma("unroll")                                                       \
    for (int k = 0; k < 16; k++) {                                          \
        float a[8], b[8];                                                   \
        *(float4*)&a[0] = *(const float4*)&(Xs)[k*132 + ty*8];              \
        *(float4*)&a[4] = *(const float4*)&(Xs)[k*132 + ty*8 + 4];          \
        *(float4*)&b[0] = *(const float4*)&(Ws)[k*132 + tx*8];              \
        *(float4*)&b[4] = *(const float4*)&(Ws)[k*132 + tx*8 + 4];          \
        _Pragma("unroll")                                                   \
        for (int i = 0; i < 8; i++)                                         \
            _Pragma("unroll")                                               \
            for (int j = 0; j < 8; j++) acc[i][j] += a[i]*b[j];             \
    }

// ---------------- fused layer: GEMM (X@W) + sparse aggregation -------------
// one CTA per graph; acc -> smem (two 64-feature passes) -> CSR gather -> out
__global__ void __launch_bounds__(256, 2)
layer_fused(const float* __restrict__ Xext, const float* __restrict__ Wg,
            const float* __restrict__ bias, int sel)
{
    __shared__ __align__(16) float sm[8960];     // 35840 B: bufs / Hs union
    float* sdv = sm + 8704;                      // beyond both regions
    int*   scn = (int*)(sm + 8832);
    const float* __restrict__ X = sel ? g_buf2 : Xext;
    const int t = threadIdx.x;
    const int tx = t & 15, ty = t >> 4;
    const int g = blockIdx.x;
    const size_t row0 = (size_t)g * 128;

    if (t < 128) {
        sdv[t] = g_dinv[g*128 + t];
        int c = ((const int*)g_A)[CNT_OFF + g*128 + t];
        scn[t] = c < ROWCAP ? c : ROWCAP;
    }

    float acc[8][8];
#pragma unroll
    for (int i = 0; i < 8; i++)
#pragma unroll
        for (int j = 0; j < 8; j++) acc[i][j] = 0.f;

    float4 pA[2], pB[2];
    const float* Xb = X + row0 * FDIM;
    LOAD_AB(Xb, FDIM, Wg, FDIM, 0)
    STORE_AB(sm)
    __syncthreads();

#pragma unroll
    for (int c = 0; c < 8; c++) {
        if (c < 7) { LOAD_AB(Xb, FDIM, Wg, FDIM, (c+1)*16) }
        const float* Xs = sm + (c & 1) * (2*CH);
        FRAG_FMA(Xs, Xs + CH)
        if (c < 7) { float* nb = sm + ((c+1) & 1) * (2*CH); STORE_AB(nb) }
        __syncthreads();
    }

    // ---- aggregation epilogue: two 64-feature passes through smem ----
    const int w = t >> 5, l = t & 31;
    const int* csr = (const int*)g_A + (size_t)g * 128 * ROWCAP;
    float* Ob = g_buf2 + row0 * FDIM;
#pragma unroll
    for (int p = 0; p < 2; p++) {
        if ((tx >> 3) == p) {                    // this thread's cols in pass p
            int cb = (tx & 7) * 8;
#pragma unroll
            for (int i = 0; i < 8; i++)
#pragma unroll
                for (int j = 0; j < 8; j++)
                    sm[(ty*8 + i)*68 + cb + j] = acc[i][j];
        }
        __syncthreads();
        const int f = p*64 + 2*l;
        const float b0 = bias[f], b1 = bias[f+1];
        for (int i = 0; i < 16; i++) {
            const int node = i*8 + w;
            const int cnt  = scn[node];
            const int* cp  = csr + node*ROWCAP;
            const float dvd = sdv[node];
            float2 hn = *(float2*)&sm[node*68 + 2*l];
            float ax = dvd*hn.x, ay = dvd*hn.y;  // self-loop term
            for (int e = 0; e < cnt; e++) {
                int s = cp[e];
                float ds = sdv[s];
                float2 h = *(float2*)&sm[s*68 + 2*l];
                ax += ds*h.x; ay += ds*h.y;
            }
            float vx = ax*dvd + b0, vy = ay*dvd + b1;
            vx = vx > 0.f ? vx : 0.f;
            vy = vy > 0.f ? vy : 0.f;
            *(float2*)(Ob + node*FDIM + f) = make_float2(vx, vy);
        }
        __syncthreads();
    }
}

// ---------------- lin1: [256,16384]@[16384,512], split-K=32, pipelined -----
__global__ void __launch_bounds__(256, 2)
lin1_gemm(const float* __restrict__ W) {
    __shared__ __align__(16) float sm[4*CH];     // 33792 B
    const int t = threadIdx.x;
    const int tx = t & 15, ty = t >> 4;
    const int col0 = blockIdx.x * 128;   // 0..3
    const int row0 = blockIdx.y * 128;   // 0..1
    const int k0   = blockIdx.z * 512;   // 0..31
    const float* __restrict__ H2 = g_buf2;       // [256,16384]

    float acc[8][8];
#pragma unroll
    for (int i = 0; i < 8; i++)
#pragma unroll
        for (int j = 0; j < 8; j++) acc[i][j] = 0.f;

    float4 pA[2], pB[2];
    const float* Ab = H2 + (size_t)row0 * 16384 + k0;
    const float* Bb = W + (size_t)k0 * MLP_H + col0;
    LOAD_AB(Ab, 16384, Bb, MLP_H, 0)
    STORE_AB(sm)
    __syncthreads();

    for (int c = 0; c < 32; c++) {
        if (c < 31) { LOAD_AB(Ab, 16384, Bb, MLP_H, (c+1)*16) }
        const float* As = sm + (c & 1) * (2*CH);
        FRAG_FMA(As, As + CH)
        if (c < 31) { float* nb = sm + ((c+1) & 1) * (2*CH); STORE_AB(nb) }
        __syncthreads();
    }

#pragma unroll
    for (int i = 0; i < 8; i++)
#pragma unroll
        for (int j = 0; j < 8; j++)
            atomicAdd(&g_mlp[(size_t)(row0 + ty*8 + i)*MLP_H + col0 + tx*8 + j],
                      acc[i][j]);
}

// ---------------- tail -----------------------------------------------------
__global__ void relu_bias_kernel(const float* __restrict__ b) {
    int i = blockIdx.x * 256 + threadIdx.x;
    if (i < B_GRAPHS*MLP_H) {
        float v = g_mlp[i] + b[i & (MLP_H-1)];
        g_mlp[i] = v > 0.f ? v : 0.f;
    }
}
__global__ void __launch_bounds__(320)
lin2_gemm(const float* __restrict__ W, const float* __restrict__ bias,
          float* __restrict__ out) {
    __shared__ float xr[MLP_H];
    const int m = blockIdx.x;
    const int w = threadIdx.x >> 5;      // 0..9
    const int lane = threadIdx.x & 31;
    for (int i = threadIdx.x; i < MLP_H; i += 320) xr[i] = g_mlp[(size_t)m*MLP_H + i];
    __syncthreads();
    float s = 0.f;
    for (int k = lane; k < MLP_H; k += 32) s += xr[k] * W[(size_t)k*OUT_DIM + w];
#pragma unroll
    for (int o = 16; o; o >>= 1) s += __shfl_xor_sync(0xffffffffu, s, o);
    if (lane == 0) out[(size_t)m*OUT_DIM + w] = s + bias[w];
}

// ---------------------------------------------------------------------------
extern "C" void kernel_launch(void* const* d_in, const int* in_sizes, int n_in,
                              void* d_out, int out_size) {
    const float* x   = (const float*)d_in[0];
    const int*   ei  = (const int*)  d_in[1];
    const float* W1  = (const float*)d_in[3];
    const float* b1  = (const float*)d_in[4];
    const float* W2  = (const float*)d_in[5];
    const float* b2  = (const float*)d_in[6];
    const float* l1w = (const float*)d_in[7];
    const float* l1b = (const float*)d_in[8];
    const float* l2w = (const float*)d_in[9];
    const float* l2b = (const float*)d_in[10];
    float* out = (float*)d_out;

    const int E = in_sizes[1] / 2;
    const int* src = ei;
    const int* dst = ei + E;
    const int eg = (E + 255) / 256;

    zero_scratch <<<512, 256>>>();
    deg_kernel   <<<eg, 256>>>(src, dst, E);    // count + csr fill
    dinv_kernel  <<<N_TOT/256, 256>>>();

    layer_fused <<<B_GRAPHS, 256>>>(x, W1, b1, 0);        // g_buf2 = layer1(x)
    layer_fused <<<B_GRAPHS, 256>>>(nullptr, W2, b2, 1);  // g_buf2 = layer2(g_buf2)

    lin1_gemm <<<dim3(4, 2, 32), 256>>>(l1w);
    relu_bias_kernel <<<(B_GRAPHS*MLP_H + 255)/256, 256>>>(l1b);
    lin2_gemm <<<B_GRAPHS, 320>>>(l2w, l2b, out);
}